// round 4
// baseline (speedup 1.0000x reference)
#include <cuda_runtime.h>
#include <cuda_bf16.h>
#include <stdint.h>
#include <math.h>

#define TM 128
#define THREADS 512
#define KC 16
#define APAD 20
#define BPAD 20
#define HP 264

// device scratch (no dynamic allocation allowed)
__device__ __align__(16) __nv_bfloat16 g_Wt[256 * 512];   // [n][k] decoder weights
__device__ __align__(16) __nv_bfloat16 g_Wp2[256 * 256];  // [p*16+c][k] head weights
__device__ float g_sums[16];
__device__ float g_cnts[16];

struct SmemT {
  __nv_bfloat16 h[128 * HP];     // activations tile, bf16
  __nv_bfloat16 As[128 * APAD];  // A k-chunk
  __nv_bfloat16 Bs[256 * BPAD];  // B k-chunk
  float Lg[128 * 17];            // selected logits
  float bias[256];
  float bpred[256];
  int em[16 * 24];
  int spair[128];
  int slabel[128];
  float psum[16];
  int pcnt[16];
};

__global__ void prep_kernel(const float* __restrict__ W1, const float* __restrict__ W2,
                            const float* __restrict__ Wp) {
  int i = blockIdx.x * blockDim.x + threadIdx.x;
  if (i < 256 * 512) {
    int n = i >> 9, k = i & 511;
    float v = (k < 256) ? W1[k * 256 + n] : W2[(k - 256) * 256 + n];
    g_Wt[n * 512 + k] = __float2bfloat16(v);
  }
  if (i < 256 * 256) {
    int col = i >> 8, k = i & 255;
    int p = col >> 4, c = col & 15;
    g_Wp2[col * 256 + k] = __float2bfloat16(Wp[p * 4096 + k * 16 + c]);
  }
  if (i < 16) { g_sums[i] = 0.f; g_cnts[i] = 0.f; }
}

__device__ __forceinline__ void mma16816(float* c, uint32_t a0, uint32_t a1, uint32_t a2,
                                         uint32_t a3, uint32_t b0, uint32_t b1) {
  asm volatile(
      "mma.sync.aligned.m16n8k16.row.col.f32.bf16.bf16.f32 "
      "{%0,%1,%2,%3}, {%4,%5,%6,%7}, {%8,%9}, {%0,%1,%2,%3};\n"
      : "+f"(c[0]), "+f"(c[1]), "+f"(c[2]), "+f"(c[3])
      : "r"(a0), "r"(a1), "r"(a2), "r"(a3), "r"(b0), "r"(b1));
}

__global__ __launch_bounds__(THREADS, 1)
void main_kernel(const float* __restrict__ h_src, const float* __restrict__ h_dst,
                 const float* __restrict__ b_dec, const float* __restrict__ b_pred,
                 const int* __restrict__ st, const int* __restrict__ dt,
                 const int* __restrict__ etc, const int* __restrict__ emap, int E) {
  extern __shared__ __align__(16) char smem_raw[];
  SmemT* S = (SmemT*)smem_raw;
  const int tid = threadIdx.x;
  const int warp = tid >> 5, lane = tid & 31;
  const int wm = warp & 3, wn = warp >> 2;
  const int e0 = blockIdx.x * TM;
  const int kq = (lane & 3) * 2;
  const int rb = lane >> 2;

  for (int i = tid; i < 256; i += THREADS) { S->bias[i] = b_dec[i]; S->bpred[i] = b_pred[i]; }
  for (int i = tid; i < 384; i += THREADS) S->em[i] = emap[i];
  if (tid < 16) { S->psum[tid] = 0.f; S->pcnt[tid] = 0; }
  __syncthreads();
  if (tid < 128) {
    int e = e0 + tid; if (e >= E) e = E - 1;
    int p = st[e] * 4 + dt[e];
    S->spair[tid] = p;
    S->slabel[tid] = S->em[p * 24 + etc[e]];
  }

  // ---- GEMM1: h = relu([h_src|h_dst] @ Wt^T + b) ----
  float acc[2][8][4];
#pragma unroll
  for (int a = 0; a < 2; a++)
#pragma unroll
    for (int b = 0; b < 8; b++)
#pragma unroll
      for (int c = 0; c < 4; c++) acc[a][b][c] = 0.f;

  const int ar = tid >> 2, ac = (tid & 3) * 4;
  int ae = e0 + ar; if (ae >= E) ae = E - 1;
  const int bn = tid >> 1, bh = (tid & 1) * 8;

  float4 av = *(const float4*)(h_src + (size_t)ae * 256 + ac);
  uint4 bv = *(const uint4*)(g_Wt + bn * 512 + bh);

  const char* Ab = (const char*)S->As;
  const char* Bb = (const char*)S->Bs;
  char* Hb = (char*)S->h;

  for (int it = 0; it < 32; ++it) {
    __syncthreads();
    {
      __nv_bfloat162 p0 = __floats2bfloat162_rn(av.x, av.y);
      __nv_bfloat162 p1 = __floats2bfloat162_rn(av.z, av.w);
      uint2 ua; ua.x = *(uint32_t*)&p0; ua.y = *(uint32_t*)&p1;
      *(uint2*)((char*)S->As + (ar * APAD + ac) * 2) = ua;
      *(uint2*)((char*)S->Bs + (bn * BPAD + bh) * 2) = make_uint2(bv.x, bv.y);
      *(uint2*)((char*)S->Bs + (bn * BPAD + bh) * 2 + 8) = make_uint2(bv.z, bv.w);
    }
    __syncthreads();
    if (it + 1 < 32) {
      int kb = (it + 1) * KC;
      const float* ap = (kb < 256) ? (h_src + (size_t)ae * 256 + kb)
                                   : (h_dst + (size_t)ae * 256 + (kb - 256));
      av = *(const float4*)(ap + ac);
      bv = *(const uint4*)(g_Wt + bn * 512 + kb + bh);
    }
    uint32_t af[2][4];
#pragma unroll
    for (int mi = 0; mi < 2; ++mi) {
      int r = wm * 32 + mi * 16 + rb;
      af[mi][0] = *(const uint32_t*)(Ab + (r * APAD + kq) * 2);
      af[mi][1] = *(const uint32_t*)(Ab + ((r + 8) * APAD + kq) * 2);
      af[mi][2] = *(const uint32_t*)(Ab + (r * APAD + kq + 8) * 2);
      af[mi][3] = *(const uint32_t*)(Ab + ((r + 8) * APAD + kq + 8) * 2);
    }
#pragma unroll
    for (int ni = 0; ni < 8; ++ni) {
      int n = wn * 64 + ni * 8 + rb;
      uint32_t b0 = *(const uint32_t*)(Bb + (n * BPAD + kq) * 2);
      uint32_t b1 = *(const uint32_t*)(Bb + (n * BPAD + kq + 8) * 2);
      mma16816(acc[0][ni], af[0][0], af[0][1], af[0][2], af[0][3], b0, b1);
      mma16816(acc[1][ni], af[1][0], af[1][1], af[1][2], af[1][3], b0, b1);
    }
  }
  __syncthreads();

  // epilogue: bias + relu -> h (bf16 in smem)
#pragma unroll
  for (int mi = 0; mi < 2; ++mi) {
    int r = wm * 32 + mi * 16 + rb;
#pragma unroll
    for (int ni = 0; ni < 8; ++ni) {
      int n0 = wn * 64 + ni * 8 + (lane & 3) * 2;
      float bb0 = S->bias[n0], bb1 = S->bias[n0 + 1];
      __nv_bfloat162 q0 = __floats2bfloat162_rn(fmaxf(acc[mi][ni][0] + bb0, 0.f),
                                                fmaxf(acc[mi][ni][1] + bb1, 0.f));
      __nv_bfloat162 q1 = __floats2bfloat162_rn(fmaxf(acc[mi][ni][2] + bb0, 0.f),
                                                fmaxf(acc[mi][ni][3] + bb1, 0.f));
      *(uint32_t*)(Hb + (r * HP + n0) * 2) = *(uint32_t*)&q0;
      *(uint32_t*)(Hb + ((r + 8) * HP + n0) * 2) = *(uint32_t*)&q1;
    }
  }

  // ---- GEMM2: logits_all = h @ Wp2^T ----
  float ac2[2][8][4];
#pragma unroll
  for (int a = 0; a < 2; a++)
#pragma unroll
    for (int b = 0; b < 8; b++)
#pragma unroll
      for (int c = 0; c < 4; c++) ac2[a][b][c] = 0.f;

  bv = *(const uint4*)(g_Wp2 + bn * 256 + bh);
  for (int it = 0; it < 16; ++it) {
    __syncthreads();
    *(uint2*)((char*)S->Bs + (bn * BPAD + bh) * 2) = make_uint2(bv.x, bv.y);
    *(uint2*)((char*)S->Bs + (bn * BPAD + bh) * 2 + 8) = make_uint2(bv.z, bv.w);
    __syncthreads();
    if (it + 1 < 16) bv = *(const uint4*)(g_Wp2 + bn * 256 + (it + 1) * 16 + bh);
    uint32_t af[2][4];
    int kk = it * 16 + kq;
#pragma unroll
    for (int mi = 0; mi < 2; ++mi) {
      int r = wm * 32 + mi * 16 + rb;
      af[mi][0] = *(const uint32_t*)(Hb + (r * HP + kk) * 2);
      af[mi][1] = *(const uint32_t*)(Hb + ((r + 8) * HP + kk) * 2);
      af[mi][2] = *(const uint32_t*)(Hb + (r * HP + kk + 8) * 2);
      af[mi][3] = *(const uint32_t*)(Hb + ((r + 8) * HP + kk + 8) * 2);
    }
#pragma unroll
    for (int ni = 0; ni < 8; ++ni) {
      int n = wn * 64 + ni * 8 + rb;
      uint32_t b0 = *(const uint32_t*)(Bb + (n * BPAD + kq) * 2);
      uint32_t b1 = *(const uint32_t*)(Bb + (n * BPAD + kq + 8) * 2);
      mma16816(ac2[0][ni], af[0][0], af[0][1], af[0][2], af[0][3], b0, b1);
      mma16816(ac2[1][ni], af[1][0], af[1][1], af[1][2], af[1][3], b0, b1);
    }
  }
  __syncthreads();

  // select each edge's pair columns into Lg
#pragma unroll
  for (int mi = 0; mi < 2; ++mi) {
    int r = wm * 32 + mi * 16 + rb;
    int plo = S->spair[r] * 16, phi = S->spair[r + 8] * 16;
#pragma unroll
    for (int ni = 0; ni < 8; ++ni) {
      int n0 = wn * 64 + ni * 8 + (lane & 3) * 2;
#pragma unroll
      for (int jj = 0; jj < 2; ++jj) {
        int c = n0 + jj;
        float bp = S->bpred[c];
        int cl = c - plo;
        if ((unsigned)cl < 16u) S->Lg[r * 17 + cl] = ac2[mi][ni][jj] + bp;
        int ch = c - phi;
        if ((unsigned)ch < 16u) S->Lg[(r + 8) * 17 + ch] = ac2[mi][ni][jj + 2] + bp;
      }
    }
  }
  __syncthreads();

  // per-edge softmax NLL + per-pair partials
  if (tid < 128) {
    int e = e0 + tid;
    if (e < E) {
      const float* L = S->Lg + tid * 17;
      float mx = -1e30f;
#pragma unroll
      for (int c = 0; c < 16; ++c) mx = fmaxf(mx, L[c]);
      float s = 0.f;
#pragma unroll
      for (int c = 0; c < 16; ++c) s += __expf(L[c] - mx);
      float l = __logf(s) + mx - L[S->slabel[tid]];
      atomicAdd(&S->psum[S->spair[tid]], l);
      atomicAdd(&S->pcnt[S->spair[tid]], 1);
    }
  }
  __syncthreads();
  if (tid < 16 && S->pcnt[tid] > 0) {
    atomicAdd(&g_sums[tid], S->psum[tid]);
    atomicAdd(&g_cnts[tid], (float)S->pcnt[tid]);
  }
}

__global__ void fin_kernel(float* out) {
  if (threadIdx.x == 0) {
    float ls = 0.f, np = 0.f;
    for (int p = 0; p < 16; ++p)
      if (g_cnts[p] > 0.f) { ls += g_sums[p] / g_cnts[p]; np += 1.f; }
    out[0] = ls / np;
  }
}

extern "C" void kernel_launch(void* const* d_in, const int* in_sizes, int n_in,
                              void* d_out, int out_size) {
  const float* h_src = (const float*)d_in[0];
  const float* h_dst = (const float*)d_in[1];
  const float* W1 = (const float*)d_in[2];
  const float* W2 = (const float*)d_in[3];
  const float* b_dec = (const float*)d_in[4];
  const float* W_pred = (const float*)d_in[5];
  const float* b_pred = (const float*)d_in[6];
  const int* st = (const int*)d_in[7];
  const int* dt = (const int*)d_in[8];
  const int* etc = (const int*)d_in[9];
  const int* em = (const int*)d_in[10];
  int E = in_sizes[7];

  cudaFuncSetAttribute(main_kernel, cudaFuncAttributeMaxDynamicSharedMemorySize,
                       (int)sizeof(SmemT));
  prep_kernel<<<512, 256>>>(W1, W2, W_pred);
  int grid = (E + TM - 1) / TM;
  main_kernel<<<grid, THREADS, sizeof(SmemT)>>>(h_src, h_dst, b_dec, b_pred, st, dt, etc, em, E);
  fin_kernel<<<1, 32>>>((float*)d_out);
}

// round 5
// speedup vs baseline: 1.3424x; 1.3424x over previous
#include <cuda_runtime.h>
#include <cuda_bf16.h>
#include <stdint.h>
#include <math.h>

#define TM 128
#define THREADS 512
#define APAD 40
#define BPAD 40
#define HP 264

// device scratch (no dynamic allocation allowed)
__device__ __align__(16) __nv_bfloat16 g_Wt[256 * 512];   // [n][k] decoder weights, bf16
__device__ __align__(16) __nv_bfloat16 g_Wp2[256 * 256];  // [p*16+c][k] head weights, bf16
__device__ float g_sums[16];
__device__ float g_cnts[16];
__device__ int g_done;

struct SmemT {
  __nv_bfloat16 As[2][128 * APAD];  // A k-chunk, double buffered (KC=32)
  __nv_bfloat16 Bs[2][256 * BPAD];  // B k-chunk, double buffered (KC=32)
  __nv_bfloat16 h[128 * HP];        // activations tile, bf16
  float Lg[128 * 17];               // selected logits
  float bias[256];
  float bpred[256];
  int em[16 * 24];
  int spair[128];
  int slabel[128];
  float psum[16];
  int pcnt[16];
};

__global__ void prep_kernel(const float* __restrict__ W1, const float* __restrict__ W2,
                            const float* __restrict__ Wp) {
  int i = blockIdx.x * blockDim.x + threadIdx.x;
  if (i < 256 * 512) {
    int n = i >> 9, k = i & 511;
    float v = (k < 256) ? W1[k * 256 + n] : W2[(k - 256) * 256 + n];
    g_Wt[n * 512 + k] = __float2bfloat16(v);
  }
  if (i < 256 * 256) {
    int col = i >> 8, k = i & 255;
    int p = col >> 4, c = col & 15;
    g_Wp2[col * 256 + k] = __float2bfloat16(Wp[p * 4096 + k * 16 + c]);
  }
  if (i < 16) { g_sums[i] = 0.f; g_cnts[i] = 0.f; }
  if (i == 0) g_done = 0;
}

__device__ __forceinline__ void mma16816(float* c, uint32_t a0, uint32_t a1, uint32_t a2,
                                         uint32_t a3, uint32_t b0, uint32_t b1) {
  asm volatile(
      "mma.sync.aligned.m16n8k16.row.col.f32.bf16.bf16.f32 "
      "{%0,%1,%2,%3}, {%4,%5,%6,%7}, {%8,%9}, {%0,%1,%2,%3};\n"
      : "+f"(c[0]), "+f"(c[1]), "+f"(c[2]), "+f"(c[3])
      : "r"(a0), "r"(a1), "r"(a2), "r"(a3), "r"(b0), "r"(b1));
}

__device__ __forceinline__ uint4 pack8(float4 a, float4 b) {
  __nv_bfloat162 p0 = __floats2bfloat162_rn(a.x, a.y);
  __nv_bfloat162 p1 = __floats2bfloat162_rn(a.z, a.w);
  __nv_bfloat162 p2 = __floats2bfloat162_rn(b.x, b.y);
  __nv_bfloat162 p3 = __floats2bfloat162_rn(b.z, b.w);
  uint4 u;
  u.x = *(uint32_t*)&p0; u.y = *(uint32_t*)&p1;
  u.z = *(uint32_t*)&p2; u.w = *(uint32_t*)&p3;
  return u;
}

__global__ __launch_bounds__(THREADS, 1)
void main_kernel(const float* __restrict__ h_src, const float* __restrict__ h_dst,
                 const float* __restrict__ b_dec, const float* __restrict__ b_pred,
                 const int* __restrict__ st, const int* __restrict__ dt,
                 const int* __restrict__ etc, const int* __restrict__ emap,
                 float* __restrict__ out, int E) {
  extern __shared__ __align__(16) char smem_raw[];
  SmemT* S = (SmemT*)smem_raw;
  const int tid = threadIdx.x;
  const int warp = tid >> 5, lane = tid & 31;
  const int wm = warp & 3, wn = warp >> 2;
  const int e0 = blockIdx.x * TM;
  const int kq = (lane & 3) * 2;
  const int rb = lane >> 2;

  for (int i = tid; i < 256; i += THREADS) { S->bias[i] = b_dec[i]; S->bpred[i] = b_pred[i]; }
  for (int i = tid; i < 384; i += THREADS) S->em[i] = emap[i];
  if (tid < 16) { S->psum[tid] = 0.f; S->pcnt[tid] = 0; }
  __syncthreads();
  if (tid < 128) {
    int e = e0 + tid; if (e >= E) e = E - 1;
    int p = st[e] * 4 + dt[e];
    S->spair[tid] = p;
    S->slabel[tid] = S->em[p * 24 + etc[e]];
  }

  // ---- GEMM1: h = relu([h_src|h_dst] @ Wt^T + b), KC=32 double-buffered ----
  float acc[2][8][4];
#pragma unroll
  for (int a = 0; a < 2; a++)
#pragma unroll
    for (int b = 0; b < 8; b++)
#pragma unroll
      for (int c = 0; c < 4; c++) acc[a][b][c] = 0.f;

  const int ar = tid >> 2, ac = (tid & 3) * 8;   // A: 128 rows x 32 k, 8 floats/thread
  int ae = e0 + ar; if (ae >= E) ae = E - 1;
  const int bn = tid >> 1, bh = (tid & 1) * 16;  // B: 256 rows x 32 k, 16 bf16/thread

  const float* apA = h_src + (size_t)ae * 256;
  float4 av0 = *(const float4*)(apA + ac);
  float4 av1 = *(const float4*)(apA + ac + 4);
  uint4 bv0 = *(const uint4*)(g_Wt + bn * 512 + bh);
  uint4 bv1 = *(const uint4*)(g_Wt + bn * 512 + bh + 8);

  *(uint4*)(&S->As[0][ar * APAD + ac]) = pack8(av0, av1);
  *(uint4*)(&S->Bs[0][bn * BPAD + bh]) = bv0;
  *(uint4*)(&S->Bs[0][bn * BPAD + bh + 8]) = bv1;
  __syncthreads();

  for (int it = 0; it < 16; ++it) {
    const int cur = it & 1;
    const bool more = (it + 1 < 16);
    if (more) {
      int kb = (it + 1) * 32;
      const float* ap = (kb < 256) ? (h_src + (size_t)ae * 256 + kb)
                                   : (h_dst + (size_t)ae * 256 + (kb - 256));
      av0 = *(const float4*)(ap + ac);
      av1 = *(const float4*)(ap + ac + 4);
      bv0 = *(const uint4*)(g_Wt + bn * 512 + kb + bh);
      bv1 = *(const uint4*)(g_Wt + bn * 512 + kb + bh + 8);
    }
    const __nv_bfloat16* Ab = S->As[cur];
    const __nv_bfloat16* Bb = S->Bs[cur];
#pragma unroll
    for (int ks = 0; ks < 2; ++ks) {
      const int kk = ks * 16 + kq;
      uint32_t af[2][4];
#pragma unroll
      for (int mi = 0; mi < 2; ++mi) {
        int r = wm * 32 + mi * 16 + rb;
        af[mi][0] = *(const uint32_t*)(Ab + r * APAD + kk);
        af[mi][1] = *(const uint32_t*)(Ab + (r + 8) * APAD + kk);
        af[mi][2] = *(const uint32_t*)(Ab + r * APAD + kk + 8);
        af[mi][3] = *(const uint32_t*)(Ab + (r + 8) * APAD + kk + 8);
      }
#pragma unroll
      for (int ni = 0; ni < 8; ++ni) {
        int n = wn * 64 + ni * 8 + rb;
        uint32_t b0 = *(const uint32_t*)(Bb + n * BPAD + kk);
        uint32_t b1 = *(const uint32_t*)(Bb + n * BPAD + kk + 8);
        mma16816(acc[0][ni], af[0][0], af[0][1], af[0][2], af[0][3], b0, b1);
        mma16816(acc[1][ni], af[1][0], af[1][1], af[1][2], af[1][3], b0, b1);
      }
    }
    if (more) {
      *(uint4*)(&S->As[cur ^ 1][ar * APAD + ac]) = pack8(av0, av1);
      *(uint4*)(&S->Bs[cur ^ 1][bn * BPAD + bh]) = bv0;
      *(uint4*)(&S->Bs[cur ^ 1][bn * BPAD + bh + 8]) = bv1;
    }
    __syncthreads();
  }

  // prefetch GEMM2 chunk 0 (overlaps epilogue)
  uint4 cv0 = *(const uint4*)(g_Wp2 + bn * 256 + bh);
  uint4 cv1 = *(const uint4*)(g_Wp2 + bn * 256 + bh + 8);

  // epilogue: bias + relu -> h (bf16 in smem)
  char* Hb = (char*)S->h;
#pragma unroll
  for (int mi = 0; mi < 2; ++mi) {
    int r = wm * 32 + mi * 16 + rb;
#pragma unroll
    for (int ni = 0; ni < 8; ++ni) {
      int n0 = wn * 64 + ni * 8 + (lane & 3) * 2;
      float bb0 = S->bias[n0], bb1 = S->bias[n0 + 1];
      __nv_bfloat162 q0 = __floats2bfloat162_rn(fmaxf(acc[mi][ni][0] + bb0, 0.f),
                                                fmaxf(acc[mi][ni][1] + bb1, 0.f));
      __nv_bfloat162 q1 = __floats2bfloat162_rn(fmaxf(acc[mi][ni][2] + bb0, 0.f),
                                                fmaxf(acc[mi][ni][3] + bb1, 0.f));
      *(uint32_t*)(Hb + (r * HP + n0) * 2) = *(uint32_t*)&q0;
      *(uint32_t*)(Hb + ((r + 8) * HP + n0) * 2) = *(uint32_t*)&q1;
    }
  }
  *(uint4*)(&S->Bs[0][bn * BPAD + bh]) = cv0;
  *(uint4*)(&S->Bs[0][bn * BPAD + bh + 8]) = cv1;
  __syncthreads();

  // ---- GEMM2: logits_all = h @ Wp2^T, KC=32 double-buffered (8 iters) ----
  float ac2[2][8][4];
#pragma unroll
  for (int a = 0; a < 2; a++)
#pragma unroll
    for (int b = 0; b < 8; b++)
#pragma unroll
      for (int c = 0; c < 4; c++) ac2[a][b][c] = 0.f;

  const __nv_bfloat16* Hh = S->h;
  for (int it = 0; it < 8; ++it) {
    const int cur = it & 1;
    const bool more = (it + 1 < 8);
    if (more) {
      int kb = (it + 1) * 32;
      cv0 = *(const uint4*)(g_Wp2 + bn * 256 + kb + bh);
      cv1 = *(const uint4*)(g_Wp2 + bn * 256 + kb + bh + 8);
    }
    const __nv_bfloat16* Bb = S->Bs[cur];
#pragma unroll
    for (int ks = 0; ks < 2; ++ks) {
      const int kk = ks * 16 + kq;        // within chunk
      const int kg = it * 32 + kk;        // global k for h
      uint32_t af[2][4];
#pragma unroll
      for (int mi = 0; mi < 2; ++mi) {
        int r = wm * 32 + mi * 16 + rb;
        af[mi][0] = *(const uint32_t*)(Hh + r * HP + kg);
        af[mi][1] = *(const uint32_t*)(Hh + (r + 8) * HP + kg);
        af[mi][2] = *(const uint32_t*)(Hh + r * HP + kg + 8);
        af[mi][3] = *(const uint32_t*)(Hh + (r + 8) * HP + kg + 8);
      }
#pragma unroll
      for (int ni = 0; ni < 8; ++ni) {
        int n = wn * 64 + ni * 8 + rb;
        uint32_t b0 = *(const uint32_t*)(Bb + n * BPAD + kk);
        uint32_t b1 = *(const uint32_t*)(Bb + n * BPAD + kk + 8);
        mma16816(ac2[0][ni], af[0][0], af[0][1], af[0][2], af[0][3], b0, b1);
        mma16816(ac2[1][ni], af[1][0], af[1][1], af[1][2], af[1][3], b0, b1);
      }
    }
    if (more) {
      *(uint4*)(&S->Bs[cur ^ 1][bn * BPAD + bh]) = cv0;
      *(uint4*)(&S->Bs[cur ^ 1][bn * BPAD + bh + 8]) = cv1;
    }
    __syncthreads();
  }

  // select each edge's pair columns into Lg
#pragma unroll
  for (int mi = 0; mi < 2; ++mi) {
    int r = wm * 32 + mi * 16 + rb;
    int plo = S->spair[r] * 16, phi = S->spair[r + 8] * 16;
#pragma unroll
    for (int ni = 0; ni < 8; ++ni) {
      int n0 = wn * 64 + ni * 8 + (lane & 3) * 2;
#pragma unroll
      for (int jj = 0; jj < 2; ++jj) {
        int c = n0 + jj;
        float bp = S->bpred[c];
        int cl = c - plo;
        if ((unsigned)cl < 16u) S->Lg[r * 17 + cl] = ac2[mi][ni][jj] + bp;
        int ch = c - phi;
        if ((unsigned)ch < 16u) S->Lg[(r + 8) * 17 + ch] = ac2[mi][ni][jj + 2] + bp;
      }
    }
  }
  __syncthreads();

  // per-edge softmax NLL + per-pair partials
  if (tid < 128) {
    int e = e0 + tid;
    if (e < E) {
      const float* L = S->Lg + tid * 17;
      float mx = -1e30f;
#pragma unroll
      for (int c = 0; c < 16; ++c) mx = fmaxf(mx, L[c]);
      float s = 0.f;
#pragma unroll
      for (int c = 0; c < 16; ++c) s += __expf(L[c] - mx);
      float l = __logf(s) + mx - L[S->slabel[tid]];
      atomicAdd(&S->psum[S->spair[tid]], l);
      atomicAdd(&S->pcnt[S->spair[tid]], 1);
    }
  }
  __syncthreads();
  if (tid < 16 && S->pcnt[tid] > 0) {
    atomicAdd(&g_sums[tid], S->psum[tid]);
    atomicAdd(&g_cnts[tid], (float)S->pcnt[tid]);
  }
  __threadfence();
  __syncthreads();

  // last CTA finalizes (fused fin kernel)
  if (tid == 0) {
    int prev = atomicAdd(&g_done, 1);
    if (prev == (int)gridDim.x - 1) {
      __threadfence();
      float ls = 0.f, np = 0.f;
#pragma unroll
      for (int p = 0; p < 16; ++p) {
        float c = g_cnts[p];
        if (c > 0.f) { ls += g_sums[p] / c; np += 1.f; }
      }
      out[0] = ls / np;
    }
  }
}

extern "C" void kernel_launch(void* const* d_in, const int* in_sizes, int n_in,
                              void* d_out, int out_size) {
  const float* h_src = (const float*)d_in[0];
  const float* h_dst = (const float*)d_in[1];
  const float* W1 = (const float*)d_in[2];
  const float* W2 = (const float*)d_in[3];
  const float* b_dec = (const float*)d_in[4];
  const float* W_pred = (const float*)d_in[5];
  const float* b_pred = (const float*)d_in[6];
  const int* st = (const int*)d_in[7];
  const int* dt = (const int*)d_in[8];
  const int* etc = (const int*)d_in[9];
  const int* em = (const int*)d_in[10];
  int E = in_sizes[7];

  cudaFuncSetAttribute(main_kernel, cudaFuncAttributeMaxDynamicSharedMemorySize,
                       (int)sizeof(SmemT));
  prep_kernel<<<512, 256>>>(W1, W2, W_pred);
  int grid = (E + TM - 1) / TM;
  main_kernel<<<grid, THREADS, sizeof(SmemT)>>>(h_src, h_dst, b_dec, b_pred, st, dt, etc, em,
                                                (float*)d_out, E);
}